// round 12
// baseline (speedup 1.0000x reference)
#include <cuda_runtime.h>
#include <cuda_fp16.h>
#include <math.h>

#define GN   256
#define NPG  512
#define NT   (GN*NPG)
#define ET   1048576
#define SAST 132     // 132*4B = 528B row stride, 16B-aligned for LDS.128

#define DSST 112
#define ACST 28

// dynamic smem layout for k_eproj_fused
#define EP_SA_OFF    0        // 52*132*4 = 27456
#define EP_SW_OFF    27456    // 52*56*8  = 23296 -> 50752
#define EP_STAGE_OFF 0        // 128*112*4 = 57344 (overlays sA/sW post-mainloop)
#define EP_SEDGE_OFF 57344    // 256*4 = 1024
#define EP_SMEM_DYN  58368

__device__ __half2 g_Eph[(size_t)ET*28];   // layer-2 gate proj, half2 [f x13|pad|s x13|pad]
__device__ float g_DS[(size_t)NT*DSST];
__device__ float g_acc[(size_t)NT*ACST];
__device__ float g_h1[(size_t)NT*26];
__device__ float g_h2[(size_t)NT*26];
__device__ float g_sm[NT];
__device__ float g_c2[GN*1920];
__device__ float g_d0[GN*512];
__device__ float g_W0T[1920*512];
__device__ float g_W1T[512*256];

__device__ __forceinline__ void fma2(unsigned long long& d, unsigned long long a,
                                     unsigned long long b) {
    asm("fma.rn.f32x2 %0, %1, %2, %0;" : "+l"(d) : "l"(a), "l"(b));
}
__device__ __forceinline__ unsigned long long bcast2(float w) {
    unsigned long long r; unsigned wi = __float_as_uint(w);
    asm("mov.b64 %0, {%1, %1};" : "=l"(r) : "r"(wi));
    return r;
}
__device__ __forceinline__ unsigned h2u(__half2 h) {
    unsigned u;
    asm("mov.b32 %0, {%1, %2};" : "=r"(u)
        : "h"(__half_as_ushort(__low2half(h))), "h"(__half_as_ushort(__high2half(h))));
    return u;
}
__device__ __forceinline__ void redv4(float* p, float a, float b, float c, float d) {
    asm volatile("red.global.add.v4.f32 [%0], {%1,%2,%3,%4};"
                 :: "l"(p), "f"(a), "f"(b), "f"(c), "f"(d) : "memory");
}

__device__ __forceinline__ void msg4(const float4 df, const float4 ds,
        const float4 sf, const float4 ss, const float4 ef, const float4 es,
        float& m0, float& m1, float& m2, float& m3) {
    float f0 = df.x+sf.x+ef.x, f1 = df.y+sf.y+ef.y;
    float f2 = df.z+sf.z+ef.z, f3 = df.w+sf.w+ef.w;
    float g0 = ds.x+ss.x+es.x, g1 = ds.y+ss.y+es.y;
    float g2 = ds.z+ss.z+es.z, g3 = ds.w+ss.w+es.w;
    m0 = (1.f/(1.f+__expf(-f0))) * ((g0>20.f)?g0:__logf(1.f+__expf(g0)));
    m1 = (1.f/(1.f+__expf(-f1))) * ((g1>20.f)?g1:__logf(1.f+__expf(g1)));
    m2 = (1.f/(1.f+__expf(-f2))) * ((g2>20.f)?g2:__logf(1.f+__expf(g2)));
    m3 = (1.f/(1.f+__expf(-f3))) * ((g3>20.f)?g3:__logf(1.f+__expf(g3)));
}

// ---- fused Eproj GEMM (both layers) + layer-1 combine; prefetch mainloop
__global__ __launch_bounds__(256) void k_eproj_fused(const float* __restrict__ ea,
        const float* __restrict__ Wf1, const float* __restrict__ Ws1,
        const float* __restrict__ Wf2, const float* __restrict__ Ws2,
        const int* __restrict__ ei) {
    extern __shared__ __align__(16) char dyn[];
    float* sA = (float*)(dyn + EP_SA_OFF);        // [k][edge], 52 x 132
    float2* sW2 = (float2*)(dyn + EP_SW_OFF);     // [k][slot], 52 x 56 pairs
    float* stage = (float*)(dyn + EP_STAGE_OFF);  // 128 x 112 (post-mainloop)
    int* sedge = (int*)(dyn + EP_SEDGE_OFF);
    int tid = threadIdx.x, eb = blockIdx.x * 128;

    for (int i = tid; i < 128*52; i += 256) {
        int e = i / 52, k = i - e*52;
        sA[k*SAST + e] = ea[(size_t)(eb + e)*52 + k];
    }
    // slot s: seg=s/14 selects matrix, idx=s%14 (13 = zero pad pair)
    for (int i = tid; i < 52*56; i += 256) {
        int k = i / 56, s = i - k*56;
        int seg = s / 14, idx = s - seg*14;
        float2 w = make_float2(0.f, 0.f);
        if (idx < 13) {
            const float* W = (seg == 0) ? Wf1 : (seg == 1) ? Ws1 : (seg == 2) ? Wf2 : Ws2;
            int r = idx * 2;
            w.x = W[r*104 + 52 + k];
            w.y = W[(r + 1)*104 + 52 + k];
        }
        sW2[k*56 + s] = w;
    }
    if (tid < 128) {
        sedge[tid*2]     = ei[eb + tid];
        sedge[tid*2 + 1] = ei[ET + eb + tid];
    }
    __syncthreads();

    int og = tid & 7, eg = tid >> 3;
    int s0 = og * 7, e0 = eg * 4;
    unsigned long long acc[4][7];
    #pragma unroll
    for (int p = 0; p < 4; p++)
        #pragma unroll
        for (int j = 0; j < 7; j++) acc[p][j] = 0ull;

    // 2-stage register prefetch: load k+1 before computing k
    float4 aC = *reinterpret_cast<const float4*>(sA + e0);
    unsigned long long wC[7];
    {
        const unsigned long long* wp = reinterpret_cast<const unsigned long long*>(sW2 + s0);
        #pragma unroll
        for (int j = 0; j < 7; j++) wC[j] = wp[j];
    }
    #pragma unroll 4
    for (int k = 0; k < 52; k++) {
        int kn = (k < 51) ? k + 1 : k;
        float4 aN = *reinterpret_cast<const float4*>(sA + kn*SAST + e0);
        unsigned long long wN[7];
        const unsigned long long* wpn =
            reinterpret_cast<const unsigned long long*>(sW2 + kn*56 + s0);
        #pragma unroll
        for (int j = 0; j < 7; j++) wN[j] = wpn[j];

        unsigned long long A0 = bcast2(aC.x), A1 = bcast2(aC.y);
        unsigned long long A2 = bcast2(aC.z), A3 = bcast2(aC.w);
        #pragma unroll
        for (int j = 0; j < 7; j++) {
            unsigned long long w = wC[j];
            fma2(acc[0][j], A0, w); fma2(acc[1][j], A1, w);
            fma2(acc[2][j], A2, w); fma2(acc[3][j], A3, w);
        }
        aC = aN;
        #pragma unroll
        for (int j = 0; j < 7; j++) wC[j] = wN[j];
    }
    __syncthreads();   // done reading sA/sW before stage overlays them

    // stage: edge-major rows of 112 floats (56 pairs); pad pairs are exact zeros
    float2* stage2 = (float2*)stage;
    #pragma unroll
    for (int p = 0; p < 4; p++)
        #pragma unroll
        for (int j = 0; j < 7; j++)
            stage2[(e0 + p)*56 + s0 + j] = *reinterpret_cast<float2*>(&acc[p][j]);
    __syncthreads();

    // flush layer-2 half as half2 (floats 56..111 of each row), coalesced
    {
        uint4* dst = reinterpret_cast<uint4*>(g_Eph + (size_t)eb*28);
        for (int i = tid; i < 896; i += 256) {
            int e = i / 7, q = i - e*7;
            const float* sp = stage + e*112 + 56 + q*8;
            __half2 h0 = __floats2half2_rn(sp[0], sp[1]);
            __half2 h1 = __floats2half2_rn(sp[2], sp[3]);
            __half2 h2 = __floats2half2_rn(sp[4], sp[5]);
            __half2 h3 = __floats2half2_rn(sp[6], sp[7]);
            dst[(size_t)e*7 + q] = make_uint4(h2u(h0), h2u(h1), h2u(h2), h2u(h3));
        }
    }
    // layer-1 combine: 128 edges x 7 chunks (fp32 from stage)
    for (int i = tid; i < 896; i += 256) {
        int el = i / 7, c = i - el*7, o = c*4;
        int s = sedge[el*2], d = sedge[el*2 + 1];
        const float* Dp = g_DS + (size_t)d*DSST;
        const float* Sp = g_DS + (size_t)s*DSST + 56;
        const float* Eb = stage + el*112;
        float4 df = *reinterpret_cast<const float4*>(Dp + o);
        float4 ds = *reinterpret_cast<const float4*>(Dp + 28 + o);
        float4 sf = *reinterpret_cast<const float4*>(Sp + o);
        float4 ss = *reinterpret_cast<const float4*>(Sp + 28 + o);
        float4 ef = *reinterpret_cast<const float4*>(Eb + o);
        float4 es = *reinterpret_cast<const float4*>(Eb + 28 + o);
        float m0, m1, m2, m3;
        msg4(df, ds, sf, ss, ef, es, m0, m1, m2, m3);
        redv4(g_acc + (size_t)d*ACST + o, m0, m1, m2, m3);
    }
}

// ---- node gate terms GEMM -> g_DS, staged coalesced stores; zero acc
__global__ __launch_bounds__(256) void k_nodeproj(const float* __restrict__ xin,
        int layer, const float* __restrict__ Wf, const float* __restrict__ Ws,
        const float* __restrict__ bf, const float* __restrict__ bs) {
    __shared__ __align__(16) char s_raw[39232];
    float* sA    = (float*)s_raw;                 // 26*132
    float* sW    = (float*)(s_raw + 13728);       // 26*104
    float* sbias = (float*)(s_raw + 24544);       // 104
    float* stage = (float*)(s_raw + 24960);       // 32*112
    int tid = threadIdx.x, nb = blockIdx.x * 128;
    const float* h = layer ? g_h1 : xin;
    for (int i = tid; i < 128*26; i += 256) {
        int n = i / 26, k = i - n*26;
        sA[k*SAST + n] = h[(size_t)(nb + n)*26 + k];
    }
    for (int i = tid; i < 26*104; i += 256) {
        int k = i / 104, o = i - k*104;
        int half = (o < 52) ? 0 : 26;
        int oo = (o < 52) ? o : o - 52;
        const float* W = (oo < 26) ? Wf : Ws;
        int r = (oo < 26) ? oo : oo - 26;
        sW[i] = W[r*104 + half + k];
    }
    if (tid < 104) sbias[tid] = (tid < 26) ? bf[tid] : (tid < 52 ? bs[tid-26] : 0.f);
    __syncthreads();
    int og = tid & 7, ng = tid >> 3;
    int o0 = og * 13, n0 = ng * 4;
    unsigned long long acc[2][13];
    #pragma unroll
    for (int p = 0; p < 2; p++)
        #pragma unroll
        for (int j = 0; j < 13; j++) acc[p][j] = 0ull;
    #pragma unroll 2
    for (int k = 0; k < 26; k++) {
        const unsigned long long* ap =
            reinterpret_cast<const unsigned long long*>(sA + k*SAST + n0);
        unsigned long long a0 = ap[0], a1 = ap[1];
        #pragma unroll
        for (int j = 0; j < 13; j++) {
            unsigned long long w2 = bcast2(sW[k*104 + o0 + j]);
            fma2(acc[0][j], a0, w2); fma2(acc[1][j], a1, w2);
        }
    }
    for (int pass = 0; pass < 4; pass++) {
        __syncthreads();
        if (ng >= pass*8 && ng < pass*8 + 8) {
            int rbase = n0 - pass*32;
            #pragma unroll
            for (int p = 0; p < 2; p++) {
                #pragma unroll
                for (int j = 0; j < 13; j++) {
                    int oo = o0 + j;
                    float bv = sbias[oo];
                    int src = (oo >= 52);
                    int ol = src ? oo - 52 : oo;
                    int off = (src ? 56 : 0) + (ol / 26) * 28 + (ol % 26);
                    float2 v = *reinterpret_cast<float2*>(&acc[p][j]);
                    stage[(rbase + 2*p)*112 + off]     = v.x + bv;
                    stage[(rbase + 2*p + 1)*112 + off] = v.y + bv;
                }
            }
        }
        __syncthreads();
        float4* dst = reinterpret_cast<float4*>(g_DS + ((size_t)nb + pass*32)*DSST);
        const float4* srcp = reinterpret_cast<const float4*>(stage);
        for (int i = tid; i < 896; i += 256) dst[i] = srcp[i];
    }
    if (tid < 128) {
        float4 z = make_float4(0.f, 0.f, 0.f, 0.f);
        float4* zp = reinterpret_cast<float4*>(g_acc + (size_t)(nb + tid)*ACST);
        #pragma unroll
        for (int q = 0; q < 7; q++) zp[q] = z;
    }
}

// ---- layer-2 per-edge combine; Ep from half2; 2 threads per edge
__device__ __forceinline__ void edge_chunk_h(const float* Dp, const float* Sp,
        const __half2* Eb, float* ap, int o) {
    int q = o >> 1;
    float4 df = *reinterpret_cast<const float4*>(Dp + o);
    float4 ds = *reinterpret_cast<const float4*>(Dp + 28 + o);
    float4 sf = *reinterpret_cast<const float4*>(Sp + o);
    float4 ss = *reinterpret_cast<const float4*>(Sp + 28 + o);
    float2 ea0 = __half22float2(__ldcs(Eb + q));
    float2 ea1 = __half22float2(__ldcs(Eb + q + 1));
    float2 eb0 = __half22float2(__ldcs(Eb + 14 + q));
    float2 eb1 = __half22float2(__ldcs(Eb + 15 + q));
    float4 ef = make_float4(ea0.x, ea0.y, ea1.x, ea1.y);
    float4 es = make_float4(eb0.x, eb0.y, eb1.x, eb1.y);
    float m0, m1, m2, m3;
    msg4(df, ds, sf, ss, ef, es, m0, m1, m2, m3);
    redv4(ap + o, m0, m1, m2, m3);
}

__global__ __launch_bounds__(512) void k_edge(const int* __restrict__ ei) {
    int t = blockIdx.x*512 + threadIdx.x;
    int e = t >> 1, half = t & 1;
    int s = ei[e], d = ei[ET + e];
    const float* Dp = g_DS + (size_t)d*DSST;
    const float* Sp = g_DS + (size_t)s*DSST + 56;
    const __half2* Eb = g_Eph + (size_t)e*28;
    float* ap = g_acc + (size_t)d*ACST;
    if (half == 0) {
        edge_chunk_h(Dp, Sp, Eb, ap, 0);
        edge_chunk_h(Dp, Sp, Eb, ap, 4);
        edge_chunk_h(Dp, Sp, Eb, ap, 8);
        edge_chunk_h(Dp, Sp, Eb, ap, 12);
    } else {
        edge_chunk_h(Dp, Sp, Eb, ap, 16);
        edge_chunk_h(Dp, Sp, Eb, ap, 20);
        edge_chunk_h(Dp, Sp, Eb, ap, 24);
    }
}

__global__ void k_finalize(const float* __restrict__ xin, int layer) {
    int n = blockIdx.x*256 + threadIdx.x;
    const float* prev = layer ? g_h1 : xin;
    float* outp = layer ? g_h2 : g_h1;
    const float* ac = g_acc + (size_t)n*ACST;
    #pragma unroll
    for (int j = 0; j < 26; j++)
        outp[(size_t)n*26 + j] = tanhf(prev[(size_t)n*26 + j] + ac[j]);
}

__global__ __launch_bounds__(256) void k_softmax(const float* __restrict__ ic) {
    __shared__ float red[256];
    int g = blockIdx.x, t = threadIdx.x;
    size_t base = (size_t)g * NPG;
    float v0 = ic[base + t], v1 = ic[base + 256 + t];
    red[t] = fmaxf(v0, v1); __syncthreads();
    for (int st = 128; st > 0; st >>= 1) {
        if (t < st) red[t] = fmaxf(red[t], red[t + st]);
        __syncthreads();
    }
    float m = red[0]; __syncthreads();
    float e0 = __expf(v0 - m), e1 = __expf(v1 - m);
    red[t] = e0 + e1; __syncthreads();
    for (int st = 128; st > 0; st >>= 1) {
        if (t < st) red[t] += red[t + st];
        __syncthreads();
    }
    float inv = 1.f / red[0];
    g_sm[base + t] = e0 * inv;
    g_sm[base + 256 + t] = e1 * inv;
}

__global__ __launch_bounds__(256) void k_sortpool(const float* __restrict__ Wc1,
        const float* __restrict__ bc1, const float* __restrict__ Wc2,
        const float* __restrict__ bc2) {
    __shared__ float sv[512];
    __shared__ unsigned short si[512];
    __shared__ float pf[128*53];
    __shared__ float m16[16*64];
    __shared__ float swc1[16*53];
    __shared__ float swc2[2560];
    __shared__ float sb1[16], sb2[32];
    int g = blockIdx.x, t = threadIdx.x;
    size_t nb = (size_t)g * NPG;
    sv[t] = g_sm[nb + t];           si[t] = (unsigned short)t;
    sv[t+256] = g_sm[nb + 256 + t]; si[t+256] = (unsigned short)(t + 256);
    for (int i = t; i < 16*53; i += 256) swc1[i] = Wc1[i];
    for (int i = t; i < 2560;  i += 256) swc2[i] = Wc2[i];
    if (t < 16) sb1[t] = bc1[t];
    if (t < 32) sb2[t] = bc2[t];
    __syncthreads();
    for (int size = 2; size <= 512; size <<= 1) {
        for (int stride = size >> 1; stride > 0; stride >>= 1) {
            int q = t / stride, r = t - q*stride;
            int i = q*2*stride + r, j = i + stride;
            bool dir = ((i & size) == 0);
            float av = sv[i], bv = sv[j];
            int ai = si[i], bi = si[j];
            bool before = (av > bv) || (av == bv && ai < bi);
            if (dir ? !before : before) {
                sv[i] = bv; sv[j] = av;
                si[i] = (unsigned short)bi; si[j] = (unsigned short)ai;
            }
            __syncthreads();
        }
    }
    for (int i = t; i < 128*53; i += 256) {
        int k = i / 53, l = i - k*53;
        int node = (int)nb + (int)si[k];
        float v;
        if (l < 26)      v = g_h1[(size_t)node*26 + l];
        else if (l < 52) v = g_h2[(size_t)node*26 + l - 26];
        else             v = sv[k];
        pf[i] = v;
    }
    __syncthreads();
    for (int task = t; task < 1024; task += 256) {
        int c = task & 15, j = task >> 4;
        const float* w  = swc1 + c*53;
        const float* p0 = pf + (2*j)*53;
        const float* p1 = p0 + 53;
        float a = sb1[c], b = sb1[c];
        #pragma unroll 13
        for (int l = 0; l < 53; l++) { a += w[l]*p0[l]; b += w[l]*p1[l]; }
        a = fmaxf(a, 0.f); b = fmaxf(b, 0.f);
        m16[c*64 + j] = fmaxf(a, b);
    }
    __syncthreads();
    for (int task = t; task < 1920; task += 256) {
        int oc = task / 60, p = task - oc*60;
        float acc = sb2[oc];
        #pragma unroll 4
        for (int ic2 = 0; ic2 < 16; ic2++) {
            const float* w  = swc2 + (oc*16 + ic2)*5;
            const float* mm = m16 + ic2*64 + p;
            #pragma unroll
            for (int u = 0; u < 5; u++) acc += w[u]*mm[u];
        }
        g_c2[g*1920 + task] = fmaxf(acc, 0.f);
    }
}

// 32x32 smem tile transpose: W0[512][1920] -> W0T[1920][512]
__global__ __launch_bounds__(256) void k_transW0(const float* __restrict__ W0) {
    __shared__ float tile[32][33];
    int k0 = blockIdx.x * 32, o0 = blockIdx.y * 32;
    int tx = threadIdx.x & 31, ty = threadIdx.x >> 5;   // 32 x 8
    #pragma unroll
    for (int r = 0; r < 32; r += 8)
        tile[ty + r][tx] = W0[(size_t)(o0 + ty + r)*1920 + k0 + tx];
    __syncthreads();
    #pragma unroll
    for (int r = 0; r < 32; r += 8)
        g_W0T[(size_t)(k0 + ty + r)*512 + o0 + tx] = tile[tx][ty + r];
}
__global__ void k_transW1(const float* __restrict__ W1) {
    int i = blockIdx.x*256 + threadIdx.x;
    int k = i >> 8, o = i & 255;
    g_W1T[i] = W1[o*512 + k];
}

__global__ __launch_bounds__(256) void k_dense0(const float* __restrict__ b0) {
    __shared__ float sA[4*1920];
    int t = threadIdx.x, gb = blockIdx.x*4;
    for (int i = t; i < 4*1920; i += 256) sA[i] = g_c2[gb*1920 + i];
    __syncthreads();
    float bb0 = b0[t], bb1 = b0[t + 256];
    float acc0[4], acc1[4];
    #pragma unroll
    for (int g2 = 0; g2 < 4; g2++) { acc0[g2] = bb0; acc1[g2] = bb1; }
    for (int k = 0; k < 1920; k++) {
        float w0 = g_W0T[k*512 + t];
        float w1 = g_W0T[k*512 + t + 256];
        #pragma unroll
        for (int g2 = 0; g2 < 4; g2++) {
            float a = sA[g2*1920 + k];
            acc0[g2] += a*w0; acc1[g2] += a*w1;
        }
    }
    #pragma unroll
    for (int g2 = 0; g2 < 4; g2++) {
        g_d0[(gb + g2)*512 + t]       = fmaxf(acc0[g2], 0.f);
        g_d0[(gb + g2)*512 + t + 256] = fmaxf(acc1[g2], 0.f);
    }
}

__global__ __launch_bounds__(256) void k_dense12(const float* __restrict__ b1,
        const float* __restrict__ W2, const float* __restrict__ b2,
        float* __restrict__ out) {
    __shared__ float sd[512];
    __shared__ float red[256];
    int g = blockIdx.x, t = threadIdx.x;
    sd[t] = g_d0[g*512 + t]; sd[t+256] = g_d0[g*512 + 256 + t];
    __syncthreads();
    float acc = b1[t];
    #pragma unroll 8
    for (int k = 0; k < 512; k++) acc += sd[k] * g_W1T[k*256 + t];
    red[t] = fmaxf(acc, 0.f) * W2[t];
    __syncthreads();
    for (int st = 128; st > 0; st >>= 1) {
        if (t < st) red[t] += red[t + st];
        __syncthreads();
    }
    if (t == 0) out[g] = red[0] + b2[0];
}

extern "C" void kernel_launch(void* const* d_in, const int* in_sizes, int n_in,
                              void* d_out, int out_size) {
    const float* x   = (const float*)d_in[0];
    const float* ea  = (const float*)d_in[1];
    const float* ic  = (const float*)d_in[2];
    const float* Wf1 = (const float*)d_in[3];
    const float* bf1 = (const float*)d_in[4];
    const float* Ws1 = (const float*)d_in[5];
    const float* bs1 = (const float*)d_in[6];
    const float* Wf2 = (const float*)d_in[7];
    const float* bf2 = (const float*)d_in[8];
    const float* Ws2 = (const float*)d_in[9];
    const float* bs2 = (const float*)d_in[10];
    const float* Wc1 = (const float*)d_in[11];
    const float* bc1 = (const float*)d_in[12];
    const float* Wc2 = (const float*)d_in[13];
    const float* bc2 = (const float*)d_in[14];
    const float* W0  = (const float*)d_in[15];
    const float* b0  = (const float*)d_in[16];
    const float* W1  = (const float*)d_in[17];
    const float* b1  = (const float*)d_in[18];
    const float* W2  = (const float*)d_in[19];
    const float* b2  = (const float*)d_in[20];
    const int*   ei  = (const int*)d_in[21];
    float* out = (float*)d_out;

    cudaFuncSetAttribute(k_eproj_fused,
                         cudaFuncAttributeMaxDynamicSharedMemorySize, EP_SMEM_DYN);

    // eproj 4th -> lands on the ncu-profiled slot
    k_transW1<<<512, 256>>>(W1);
    k_softmax<<<GN, 256>>>(ic);
    k_nodeproj<<<NT/128, 256>>>(x, 0, Wf1, Ws1, bf1, bs1);
    k_eproj_fused<<<ET/128, 256, EP_SMEM_DYN>>>(ea, Wf1, Ws1, Wf2, Ws2, ei);
    k_transW0<<<dim3(60, 16), 256>>>(W0);
    k_finalize<<<NT/256, 256>>>(x, 0);

    k_nodeproj<<<NT/128, 256>>>(x, 1, Wf2, Ws2, bf2, bs2);
    k_edge<<<ET/256, 512>>>(ei);
    k_finalize<<<NT/256, 256>>>(x, 1);

    k_sortpool<<<GN, 256>>>(Wc1, bc1, Wc2, bc2);
    k_dense0<<<GN/4, 256>>>(b0);
    k_dense12<<<GN, 256>>>(b1, W2, b2, out);
}

// round 14
// speedup vs baseline: 1.1657x; 1.1657x over previous
#include <cuda_runtime.h>
#include <cuda_fp16.h>
#include <math.h>

#define GN   256
#define NPG  512
#define NT   (GN*NPG)
#define ET   1048576
#define SAST 132

#define DSST 112
#define ACST 28

// dynamic smem for k_eproj_fused (tf32 mma version)
#define EP_SA_OFF    0        // 56*136*4 = 30464 (tf32 A, [k][edge] stride 136)
#define EP_SW_OFF    30464    // 56*104*4 = 23296 -> 53760 (tf32 W^T, [k][o])
#define EP_STAGE_OFF 0        // 128*112*4 = 57344 (overlays sA/sW post-mainloop)
#define EP_SEDGE_OFF 57344    // 256*4
#define EP_SMEM_DYN  58368

__device__ __half2 g_Eph[(size_t)ET*28];   // layer-2 gate proj, half2
__device__ float g_DS[(size_t)NT*DSST];
__device__ float g_acc[(size_t)NT*ACST];
__device__ float g_h1[(size_t)NT*26];
__device__ float g_h2[(size_t)NT*26];
__device__ float g_sm[NT];
__device__ float g_c2[GN*1920];
__device__ float g_d0[GN*512];
__device__ float g_W0T[1920*512];
__device__ float g_W1T[512*256];

__device__ __forceinline__ void fma2(unsigned long long& d, unsigned long long a,
                                     unsigned long long b) {
    asm("fma.rn.f32x2 %0, %1, %2, %0;" : "+l"(d) : "l"(a), "l"(b));
}
__device__ __forceinline__ unsigned long long bcast2(float w) {
    unsigned long long r; unsigned wi = __float_as_uint(w);
    asm("mov.b64 %0, {%1, %1};" : "=l"(r) : "r"(wi));
    return r;
}
__device__ __forceinline__ unsigned h2u(__half2 h) {
    unsigned u;
    asm("mov.b32 %0, {%1, %2};" : "=r"(u)
        : "h"(__half_as_ushort(__low2half(h))), "h"(__half_as_ushort(__high2half(h))));
    return u;
}
__device__ __forceinline__ unsigned f2tf32(float f) {
    unsigned r; asm("cvt.rna.tf32.f32 %0, %1;" : "=r"(r) : "f"(f)); return r;
}
__device__ __forceinline__ void mma_tf32(float4& c, unsigned a0, unsigned a1,
        unsigned a2, unsigned a3, unsigned b0, unsigned b1) {
    asm("mma.sync.aligned.m16n8k8.row.col.f32.tf32.tf32.f32 "
        "{%0,%1,%2,%3}, {%4,%5,%6,%7}, {%8,%9}, {%0,%1,%2,%3};"
        : "+f"(c.x), "+f"(c.y), "+f"(c.z), "+f"(c.w)
        : "r"(a0), "r"(a1), "r"(a2), "r"(a3), "r"(b0), "r"(b1));
}
__device__ __forceinline__ void redv4(float* p, float a, float b, float c, float d) {
    asm volatile("red.global.add.v4.f32 [%0], {%1,%2,%3,%4};"
                 :: "l"(p), "f"(a), "f"(b), "f"(c), "f"(d) : "memory");
}

__device__ __forceinline__ void msg4(const float4 df, const float4 ds,
        const float4 sf, const float4 ss, const float4 ef, const float4 es,
        float& m0, float& m1, float& m2, float& m3) {
    float f0 = df.x+sf.x+ef.x, f1 = df.y+sf.y+ef.y;
    float f2 = df.z+sf.z+ef.z, f3 = df.w+sf.w+ef.w;
    float g0 = ds.x+ss.x+es.x, g1 = ds.y+ss.y+es.y;
    float g2 = ds.z+ss.z+es.z, g3 = ds.w+ss.w+es.w;
    m0 = (1.f/(1.f+__expf(-f0))) * ((g0>20.f)?g0:__logf(1.f+__expf(g0)));
    m1 = (1.f/(1.f+__expf(-f1))) * ((g1>20.f)?g1:__logf(1.f+__expf(g1)));
    m2 = (1.f/(1.f+__expf(-f2))) * ((g2>20.f)?g2:__logf(1.f+__expf(g2)));
    m3 = (1.f/(1.f+__expf(-f3))) * ((g3>20.f)?g3:__logf(1.f+__expf(g3)));
}

// ---- fused Eproj via tf32 tensor mma + layer-1 combine
__global__ __launch_bounds__(256) void k_eproj_fused(const float* __restrict__ ea,
        const float* __restrict__ Wf1, const float* __restrict__ Ws1,
        const float* __restrict__ Wf2, const float* __restrict__ Ws2,
        const int* __restrict__ ei) {
    extern __shared__ __align__(16) char dyn[];
    unsigned* sAu = (unsigned*)(dyn + EP_SA_OFF);   // [k 0..55][edge 0..127] stride 136
    unsigned* sWu = (unsigned*)(dyn + EP_SW_OFF);   // [k 0..55][o 0..103] stride 104
    float* stage  = (float*)(dyn + EP_STAGE_OFF);   // 128 x 112 (post-mainloop)
    int* sedge    = (int*)(dyn + EP_SEDGE_OFF);
    int tid = threadIdx.x, eb = blockIdx.x * 128;

    for (int i = tid; i < 128*52; i += 256) {
        int e = i / 52, k = i - e*52;
        sAu[k*136 + e] = f2tf32(ea[(size_t)(eb + e)*52 + k]);
    }
    for (int i = tid; i < 4*128; i += 256) {           // zero K-pad rows 52..55
        int k = 52 + i / 128, e = i & 127;
        sAu[k*136 + e] = 0u;
    }
    for (int i = tid; i < 56*104; i += 256) {
        int k = i / 104, o = i - k*104;
        float v = 0.f;
        if (k < 52) {
            const float* W; int r;
            if      (o < 26) { W = Wf1; r = o;      }
            else if (o < 52) { W = Ws1; r = o - 26; }
            else if (o < 78) { W = Wf2; r = o - 52; }
            else             { W = Ws2; r = o - 78; }
            v = W[r*104 + 52 + k];
        }
        sWu[i] = f2tf32(v);
    }
    if (tid < 128) {
        sedge[tid*2]     = ei[eb + tid];
        sedge[tid*2 + 1] = ei[ET + eb + tid];
    }
    __syncthreads();

    int wid = tid >> 5, lane = tid & 31;
    int grp = lane >> 2, tig = lane & 3;
    int e0 = wid * 16;
    float4 c[13];
    #pragma unroll
    for (int n = 0; n < 13; n++) c[n] = make_float4(0.f, 0.f, 0.f, 0.f);

    #pragma unroll
    for (int ks = 0; ks < 7; ks++) {
        int kk = ks * 8;
        unsigned a0 = sAu[(kk + tig)*136 + e0 + grp];
        unsigned a1 = sAu[(kk + tig)*136 + e0 + grp + 8];
        unsigned a2 = sAu[(kk + tig + 4)*136 + e0 + grp];
        unsigned a3 = sAu[(kk + tig + 4)*136 + e0 + grp + 8];
        #pragma unroll
        for (int n = 0; n < 13; n++) {
            unsigned b0 = sWu[(kk + tig)*104 + n*8 + grp];
            unsigned b1 = sWu[(kk + tig + 4)*104 + n*8 + grp];
            mma_tf32(c[n], a0, a1, a2, a3, b0, b1);
        }
    }
    __syncthreads();   // mainloop done before stage overlays sA/sW

    // scatter C into stage (padded 112-float rows); pads left uninit (consumers pad-safe)
    {
        int e_lo = e0 + grp, e_hi = e_lo + 8;
        #pragma unroll
        for (int n = 0; n < 13; n++) {
            int o0 = n*8 + tig*2;
            int f0 = (o0 / 26) * 28 + (o0 % 26);
            int o1 = o0 + 1;
            int f1 = (o1 / 26) * 28 + (o1 % 26);
            stage[e_lo*112 + f0] = c[n].x;
            stage[e_lo*112 + f1] = c[n].y;
            stage[e_hi*112 + f0] = c[n].z;
            stage[e_hi*112 + f1] = c[n].w;
        }
    }
    __syncthreads();

    // flush layer-2 half as half2, coalesced
    {
        uint4* dst = reinterpret_cast<uint4*>(g_Eph + (size_t)eb*28);
        for (int i = tid; i < 896; i += 256) {
            int e = i / 7, q = i - e*7;
            const float* sp = stage + e*112 + 56 + q*8;
            __half2 h0 = __floats2half2_rn(sp[0], sp[1]);
            __half2 h1 = __floats2half2_rn(sp[2], sp[3]);
            __half2 h2 = __floats2half2_rn(sp[4], sp[5]);
            __half2 h3 = __floats2half2_rn(sp[6], sp[7]);
            dst[(size_t)e*7 + q] = make_uint4(h2u(h0), h2u(h1), h2u(h2), h2u(h3));
        }
    }
    // layer-1 combine: 128 edges x 7 chunks
    for (int i = tid; i < 896; i += 256) {
        int el = i / 7, cc = i - el*7, o = cc*4;
        int s = sedge[el*2], d = sedge[el*2 + 1];
        const float* Dp = g_DS + (size_t)d*DSST;
        const float* Sp = g_DS + (size_t)s*DSST + 56;
        const float* Eb = stage + el*112;
        float4 df = *reinterpret_cast<const float4*>(Dp + o);
        float4 ds = *reinterpret_cast<const float4*>(Dp + 28 + o);
        float4 sf = *reinterpret_cast<const float4*>(Sp + o);
        float4 ss = *reinterpret_cast<const float4*>(Sp + 28 + o);
        float4 ef = *reinterpret_cast<const float4*>(Eb + o);
        float4 es = *reinterpret_cast<const float4*>(Eb + 28 + o);
        float m0, m1, m2, m3;
        msg4(df, ds, sf, ss, ef, es, m0, m1, m2, m3);
        redv4(g_acc + (size_t)d*ACST + o, m0, m1, m2, m3);
    }
}

// ---- node gate terms GEMM -> g_DS (f32x2 path, unchanged); zero acc
__global__ __launch_bounds__(256) void k_nodeproj(const float* __restrict__ xin,
        int layer, const float* __restrict__ Wf, const float* __restrict__ Ws,
        const float* __restrict__ bf, const float* __restrict__ bs) {
    __shared__ __align__(16) char s_raw[39232];
    float* sA    = (float*)s_raw;
    float* sW    = (float*)(s_raw + 13728);
    float* sbias = (float*)(s_raw + 24544);
    float* stage = (float*)(s_raw + 24960);
    int tid = threadIdx.x, nb = blockIdx.x * 128;
    const float* h = layer ? g_h1 : xin;
    for (int i = tid; i < 128*26; i += 256) {
        int n = i / 26, k = i - n*26;
        sA[k*SAST + n] = h[(size_t)(nb + n)*26 + k];
    }
    for (int i = tid; i < 26*104; i += 256) {
        int k = i / 104, o = i - k*104;
        int half = (o < 52) ? 0 : 26;
        int oo = (o < 52) ? o : o - 52;
        const float* W = (oo < 26) ? Wf : Ws;
        int r = (oo < 26) ? oo : oo - 26;
        sW[i] = W[r*104 + half + k];
    }
    if (tid < 104) sbias[tid] = (tid < 26) ? bf[tid] : (tid < 52 ? bs[tid-26] : 0.f);
    __syncthreads();
    int og = tid & 7, ng = tid >> 3;
    int o0 = og * 13, n0 = ng * 4;
    unsigned long long acc[2][13];
    #pragma unroll
    for (int p = 0; p < 2; p++)
        #pragma unroll
        for (int j = 0; j < 13; j++) acc[p][j] = 0ull;
    #pragma unroll 2
    for (int k = 0; k < 26; k++) {
        const unsigned long long* ap =
            reinterpret_cast<const unsigned long long*>(sA + k*SAST + n0);
        unsigned long long a0 = ap[0], a1 = ap[1];
        #pragma unroll
        for (int j = 0; j < 13; j++) {
            unsigned long long w2 = bcast2(sW[k*104 + o0 + j]);
            fma2(acc[0][j], a0, w2); fma2(acc[1][j], a1, w2);
        }
    }
    for (int pass = 0; pass < 4; pass++) {
        __syncthreads();
        if (ng >= pass*8 && ng < pass*8 + 8) {
            int rbase = n0 - pass*32;
            #pragma unroll
            for (int p = 0; p < 2; p++) {
                #pragma unroll
                for (int j = 0; j < 13; j++) {
                    int oo = o0 + j;
                    float bv = sbias[oo];
                    int src = (oo >= 52);
                    int ol = src ? oo - 52 : oo;
                    int off = (src ? 56 : 0) + (ol / 26) * 28 + (ol % 26);
                    float2 v = *reinterpret_cast<float2*>(&acc[p][j]);
                    stage[(rbase + 2*p)*112 + off]     = v.x + bv;
                    stage[(rbase + 2*p + 1)*112 + off] = v.y + bv;
                }
            }
        }
        __syncthreads();
        float4* dst = reinterpret_cast<float4*>(g_DS + ((size_t)nb + pass*32)*DSST);
        const float4* srcp = reinterpret_cast<const float4*>(stage);
        for (int i = tid; i < 896; i += 256) dst[i] = srcp[i];
    }
    if (tid < 128) {
        float4 z = make_float4(0.f, 0.f, 0.f, 0.f);
        float4* zp = reinterpret_cast<float4*>(g_acc + (size_t)(nb + tid)*ACST);
        #pragma unroll
        for (int q = 0; q < 7; q++) zp[q] = z;
    }
}

// ---- layer-2 per-edge combine; Ep from half2; 2 threads per edge
__device__ __forceinline__ void edge_chunk_h(const float* Dp, const float* Sp,
        const __half2* Eb, float* ap, int o) {
    int q = o >> 1;
    float4 df = *reinterpret_cast<const float4*>(Dp + o);
    float4 ds = *reinterpret_cast<const float4*>(Dp + 28 + o);
    float4 sf = *reinterpret_cast<const float4*>(Sp + o);
    float4 ss = *reinterpret_cast<const float4*>(Sp + 28 + o);
    float2 ea0 = __half22float2(__ldcs(Eb + q));
    float2 ea1 = __half22float2(__ldcs(Eb + q + 1));
    float2 eb0 = __half22float2(__ldcs(Eb + 14 + q));
    float2 eb1 = __half22float2(__ldcs(Eb + 15 + q));
    float4 ef = make_float4(ea0.x, ea0.y, ea1.x, ea1.y);
    float4 es = make_float4(eb0.x, eb0.y, eb1.x, eb1.y);
    float m0, m1, m2, m3;
    msg4(df, ds, sf, ss, ef, es, m0, m1, m2, m3);
    redv4(ap + o, m0, m1, m2, m3);
}

__global__ __launch_bounds__(512) void k_edge(const int* __restrict__ ei) {
    int t = blockIdx.x*512 + threadIdx.x;
    int e = t >> 1, half = t & 1;
    int s = ei[e], d = ei[ET + e];
    const float* Dp = g_DS + (size_t)d*DSST;
    const float* Sp = g_DS + (size_t)s*DSST + 56;
    const __half2* Eb = g_Eph + (size_t)e*28;
    float* ap = g_acc + (size_t)d*ACST;
    if (half == 0) {
        edge_chunk_h(Dp, Sp, Eb, ap, 0);
        edge_chunk_h(Dp, Sp, Eb, ap, 4);
        edge_chunk_h(Dp, Sp, Eb, ap, 8);
        edge_chunk_h(Dp, Sp, Eb, ap, 12);
    } else {
        edge_chunk_h(Dp, Sp, Eb, ap, 16);
        edge_chunk_h(Dp, Sp, Eb, ap, 20);
        edge_chunk_h(Dp, Sp, Eb, ap, 24);
    }
}

__global__ void k_finalize(const float* __restrict__ xin, int layer) {
    int n = blockIdx.x*256 + threadIdx.x;
    const float* prev = layer ? g_h1 : xin;
    float* outp = layer ? g_h2 : g_h1;
    const float* ac = g_acc + (size_t)n*ACST;
    #pragma unroll
    for (int j = 0; j < 26; j++)
        outp[(size_t)n*26 + j] = tanhf(prev[(size_t)n*26 + j] + ac[j]);
}

__global__ __launch_bounds__(256) void k_softmax(const float* __restrict__ ic) {
    __shared__ float red[256];
    int g = blockIdx.x, t = threadIdx.x;
    size_t base = (size_t)g * NPG;
    float v0 = ic[base + t], v1 = ic[base + 256 + t];
    red[t] = fmaxf(v0, v1); __syncthreads();
    for (int st = 128; st > 0; st >>= 1) {
        if (t < st) red[t] = fmaxf(red[t], red[t + st]);
        __syncthreads();
    }
    float m = red[0]; __syncthreads();
    float e0 = __expf(v0 - m), e1 = __expf(v1 - m);
    red[t] = e0 + e1; __syncthreads();
    for (int st = 128; st > 0; st >>= 1) {
        if (t < st) red[t] += red[t + st];
        __syncthreads();
    }
    float inv = 1.f / red[0];
    g_sm[base + t] = e0 * inv;
    g_sm[base + 256 + t] = e1 * inv;
}

__global__ __launch_bounds__(256) void k_sortpool(const float* __restrict__ Wc1,
        const float* __restrict__ bc1, const float* __restrict__ Wc2,
        const float* __restrict__ bc2) {
    __shared__ float sv[512];
    __shared__ unsigned short si[512];
    __shared__ float pf[128*53];
    __shared__ float m16[16*64];
    __shared__ float swc1[16*53];
    __shared__ float swc2[2560];
    __shared__ float sb1[16], sb2[32];
    int g = blockIdx.x, t = threadIdx.x;
    size_t nb = (size_t)g * NPG;
    sv[t] = g_sm[nb + t];           si[t] = (unsigned short)t;
    sv[t+256] = g_sm[nb + 256 + t]; si[t+256] = (unsigned short)(t + 256);
    for (int i = t; i < 16*53; i += 256) swc1[i] = Wc1[i];
    for (int i = t; i < 2560;  i += 256) swc2[i] = Wc2[i];
    if (t < 16) sb1[t] = bc1[t];
    if (t < 32) sb2[t] = bc2[t];
    __syncthreads();
    for (int size = 2; size <= 512; size <<= 1) {
        for (int stride = size >> 1; stride > 0; stride >>= 1) {
            int q = t / stride, r = t - q*stride;
            int i = q*2*stride + r, j = i + stride;
            bool dir = ((i & size) == 0);
            float av = sv[i], bv = sv[j];
            int ai = si[i], bi = si[j];
            bool before = (av > bv) || (av == bv && ai < bi);
            if (dir ? !before : before) {
                sv[i] = bv; sv[j] = av;
                si[i] = (unsigned short)bi; si[j] = (unsigned short)ai;
            }
            __syncthreads();
        }
    }
    for (int i = t; i < 128*53; i += 256) {
        int k = i / 53, l = i - k*53;
        int node = (int)nb + (int)si[k];
        float v;
        if (l < 26)      v = g_h1[(size_t)node*26 + l];
        else if (l < 52) v = g_h2[(size_t)node*26 + l - 26];
        else             v = sv[k];
        pf[i] = v;
    }
    __syncthreads();
    for (int task = t; task < 1024; task += 256) {
        int c = task & 15, j = task >> 4;
        const float* w  = swc1 + c*53;
        const float* p0 = pf + (2*j)*53;
        const float* p1 = p0 + 53;
        float a = sb1[c], b = sb1[c];
        #pragma unroll 13
        for (int l = 0; l < 53; l++) { a += w[l]*p0[l]; b += w[l]*p1[l]; }
        a = fmaxf(a, 0.f); b = fmaxf(b, 0.f);
        m16[c*64 + j] = fmaxf(a, b);
    }
    __syncthreads();
    for (int task = t; task < 1920; task += 256) {
        int oc = task / 60, p = task - oc*60;
        float acc = sb2[oc];
        #pragma unroll 4
        for (int ic2 = 0; ic2 < 16; ic2++) {
            const float* w  = swc2 + (oc*16 + ic2)*5;
            const float* mm = m16 + ic2*64 + p;
            #pragma unroll
            for (int u = 0; u < 5; u++) acc += w[u]*mm[u];
        }
        g_c2[g*1920 + task] = fmaxf(acc, 0.f);
    }
}

__global__ __launch_bounds__(256) void k_transW0(const float* __restrict__ W0) {
    __shared__ float tile[32][33];
    int k0 = blockIdx.x * 32, o0 = blockIdx.y * 32;
    int tx = threadIdx.x & 31, ty = threadIdx.x >> 5;
    #pragma unroll
    for (int r = 0; r < 32; r += 8)
        tile[ty + r][tx] = W0[(size_t)(o0 + ty + r)*1920 + k0 + tx];
    __syncthreads();
    #pragma unroll
    for (int r = 0; r < 32; r += 8)
        g_W0T[(size_t)(k0 + ty + r)*512 + o0 + tx] = tile[tx][ty + r];
}
__global__ void k_transW1(const float* __restrict__ W1) {
    int i = blockIdx.x*256 + threadIdx.x;
    int k = i >> 8, o = i & 255;
    g_W1T[i] = W1[o*512 + k];
}

__global__ __launch_bounds__(256) void k_dense0(const float* __restrict__ b0) {
    __shared__ float sA[4*1920];
    int t = threadIdx.x, gb = blockIdx.x*4;
    for (int i = t; i < 4*1920; i += 256) sA[i] = g_c2[gb*1920 + i];
    __syncthreads();
    float bb0 = b0[t], bb1 = b0[t + 256];
    float acc0[4], acc1[4];
    #pragma unroll
    for (int g2 = 0; g2 < 4; g2++) { acc0[g2] = bb0; acc1[g2] = bb1; }
    for (int k = 0; k < 1920; k++) {
        float w0 = g_W0T[k*512 + t];
        float w1 = g_W0T[k*512 + t + 256];
        #pragma unroll
        for (int g2 = 0; g2 < 4; g2++) {
            float a = sA[g2*1920 + k];
            acc0[g2] += a*w0; acc1[g2] += a*w1;
        }
    }
    #pragma unroll
    for (int g2 = 0; g2 < 4; g2++) {
        g_d0[(gb + g2)*512 + t]       = fmaxf(acc0[g2], 0.f);
        g_d0[(gb + g2)*512 + t + 256] = fmaxf(acc1[g2], 0.f);
    }
}

__global__ __launch_bounds__(256) void k_dense12(const float* __restrict__ b1,
        const float* __restrict__ W2, const float* __restrict__ b2,
        float* __restrict__ out) {
    __shared__ float sd[512];
    __shared__ float red[256];
    int g = blockIdx.x, t = threadIdx.x;
    sd[t] = g_d0[g*512 + t]; sd[t+256] = g_d0[g*512 + 256 + t];
    __syncthreads();
    float acc = b1[t];
    #pragma unroll 8
    for (int k = 0; k < 512; k++) acc += sd[k] * g_W1T[k*256 + t];
    red[t] = fmaxf(acc, 0.f) * W2[t];
    __syncthreads();
    for (int st = 128; st > 0; st >>= 1) {
        if (t < st) red[t] += red[t + st];
        __syncthreads();
    }
    if (t == 0) out[g] = red[0] + b2[0];
}

extern "C" void kernel_launch(void* const* d_in, const int* in_sizes, int n_in,
                              void* d_out, int out_size) {
    const float* x   = (const float*)d_in[0];
    const float* ea  = (const float*)d_in[1];
    const float* ic  = (const float*)d_in[2];
    const float* Wf1 = (const float*)d_in[3];
    const float* bf1 = (const float*)d_in[4];
    const float* Ws1 = (const float*)d_in[5];
    const float* bs1 = (const float*)d_in[6];
    const float* Wf2 = (const float*)d_in[7];
    const float* bf2 = (const float*)d_in[8];
    const float* Ws2 = (const float*)d_in[9];
    const float* bs2 = (const float*)d_in[10];
    const float* Wc1 = (const float*)d_in[11];
    const float* bc1 = (const float*)d_in[12];
    const float* Wc2 = (const float*)d_in[13];
    const float* bc2 = (const float*)d_in[14];
    const float* W0  = (const float*)d_in[15];
    const float* b0  = (const float*)d_in[16];
    const float* W1  = (const float*)d_in[17];
    const float* b1  = (const float*)d_in[18];
    const float* W2  = (const float*)d_in[19];
    const float* b2  = (const float*)d_in[20];
    const int*   ei  = (const int*)d_in[21];
    float* out = (float*)d_out;

    cudaFuncSetAttribute(k_eproj_fused,
                         cudaFuncAttributeMaxDynamicSharedMemorySize, EP_SMEM_DYN);

    // eproj 4th -> lands on the ncu-profiled slot
    k_transW1<<<512, 256>>>(W1);
    k_softmax<<<GN, 256>>>(ic);
    k_nodeproj<<<NT/128, 256>>>(x, 0, Wf1, Ws1, bf1, bs1);
    k_eproj_fused<<<ET/128, 256, EP_SMEM_DYN>>>(ea, Wf1, Ws1, Wf2, Ws2, ei);
    k_transW0<<<dim3(60, 16), 256>>>(W0);
    k_finalize<<<NT/256, 256>>>(x, 0);

    k_nodeproj<<<NT/128, 256>>>(x, 1, Wf2, Ws2, bf2, bs2);
    k_edge<<<ET/256, 512>>>(ei);
    k_finalize<<<NT/256, 256>>>(x, 1);

    k_sortpool<<<GN, 256>>>(Wc1, bc1, Wc2, bc2);
    k_dense0<<<GN/4, 256>>>(b0);
    k_dense12<<<GN, 256>>>(b1, W2, b2, out);
}